// round 2
// baseline (speedup 1.0000x reference)
#include <cuda_runtime.h>
#include <math.h>

#define D 128
#define CLS 10
#define GMAX 512
#define NMAX 100096
#define BN_EPS 1e-5f

// ---------------- scratch (no allocation allowed) ----------------
__device__ float g_buf0[(size_t)NMAX * D];   // GEMM output H
__device__ float g_buf1[(size_t)NMAX * D];   // aggregation output
__device__ float g_deg[NMAX];
__device__ float g_dinv[NMAX];
__device__ float g_stats[2 * D];             // column sum, sumsq
__device__ float g_pooled[GMAX * D];
__device__ float g_cnt[GMAX];

// ---------------- init ----------------
__global__ void k_init(int n) {
    int i = blockIdx.x * blockDim.x + threadIdx.x;
    if (i < n) g_deg[i] = 1.0f;           // self-loop contributes 1
    if (i < GMAX * D) g_pooled[i] = 0.0f;
    if (i < GMAX) g_cnt[i] = 0.0f;
}

__global__ void k_zerostats() {
    int i = threadIdx.x;
    if (i < 2 * D) g_stats[i] = 0.0f;
}

__global__ void k_deg(const int* __restrict__ ei, int E) {
    int e = blockIdx.x * blockDim.x + threadIdx.x;
    if (e < E) atomicAdd(&g_deg[ei[E + e]], 1.0f);
}

__global__ void k_dinv(int n) {
    int i = blockIdx.x * blockDim.x + threadIdx.x;
    if (i < n) g_dinv[i] = rsqrtf(fmaxf(g_deg[i], 1.0f));
}

// ---------------- SGEMM: C[M,128] = A[M,128] @ W[128,128] ----------------
// 128x128 tile per block, BK=16, 256 threads, 8x8 micro-tile.
__global__ __launch_bounds__(256, 2) void k_gemm(const float* __restrict__ A,
                                                 const float* __restrict__ W,
                                                 float* __restrict__ Cout, int M) {
    __shared__ float sA[16][132];   // [k][m], padded for store conflicts + alignment
    __shared__ float sW[16][128];   // [k][n]

    int tid = threadIdx.x;
    int ty = tid >> 4;       // 0..15 (m groups)
    int tx = tid & 15;       // 0..15 (n groups)
    int m0 = blockIdx.x * 128;

    float acc[8][8];
#pragma unroll
    for (int i = 0; i < 8; i++)
#pragma unroll
        for (int j = 0; j < 8; j++) acc[i][j] = 0.0f;

    for (int kk = 0; kk < 128; kk += 16) {
        // load A tile: 128 rows x 16 cols = 512 float4, 2 per thread (transposed store)
#pragma unroll
        for (int i = 0; i < 2; i++) {
            int idx = tid + i * 256;
            int m = idx >> 2;
            int q = idx & 3;
            float4 v;
            if (m0 + m < M)
                v = *(const float4*)(A + (size_t)(m0 + m) * 128 + kk + q * 4);
            else
                v = make_float4(0.f, 0.f, 0.f, 0.f);
            sA[q * 4 + 0][m] = v.x;
            sA[q * 4 + 1][m] = v.y;
            sA[q * 4 + 2][m] = v.z;
            sA[q * 4 + 3][m] = v.w;
        }
        // load W tile: 16 x 128 = 512 float4, 2 per thread
#pragma unroll
        for (int i = 0; i < 2; i++) {
            int idx = tid + i * 256;
            int k = idx >> 5;
            int q = idx & 31;
            *(float4*)&sW[k][q * 4] = *(const float4*)(W + (size_t)(kk + k) * 128 + q * 4);
        }
        __syncthreads();

#pragma unroll
        for (int k = 0; k < 16; k++) {
            float ra[8], rb[8];
            *(float4*)&ra[0] = *(float4*)&sA[k][ty * 8];
            *(float4*)&ra[4] = *(float4*)&sA[k][ty * 8 + 4];
            *(float4*)&rb[0] = *(float4*)&sW[k][tx * 8];
            *(float4*)&rb[4] = *(float4*)&sW[k][tx * 8 + 4];
#pragma unroll
            for (int i = 0; i < 8; i++)
#pragma unroll
                for (int j = 0; j < 8; j++) acc[i][j] = fmaf(ra[i], rb[j], acc[i][j]);
        }
        __syncthreads();
    }

#pragma unroll
    for (int i = 0; i < 8; i++) {
        int m = m0 + ty * 8 + i;
        if (m < M) {
            float4 v0 = make_float4(acc[i][0], acc[i][1], acc[i][2], acc[i][3]);
            float4 v1 = make_float4(acc[i][4], acc[i][5], acc[i][6], acc[i][7]);
            *(float4*)(Cout + (size_t)m * 128 + tx * 8) = v0;
            *(float4*)(Cout + (size_t)m * 128 + tx * 8 + 4) = v1;
        }
    }
}

// ---------------- self-loop init: Out[i] = H[i] * dinv[i]^2 ----------------
__global__ void k_selfinit(const float* __restrict__ H, float* __restrict__ Out, int n) {
    int i = blockIdx.x * blockDim.x + threadIdx.x;  // over n*32 float4s
    int row = i >> 5;
    int q = i & 31;
    if (row < n) {
        float s = g_dinv[row];
        s *= s;
        float4 v = *(const float4*)(H + (size_t)row * 128 + q * 4);
        v.x *= s; v.y *= s; v.z *= s; v.w *= s;
        *(float4*)(Out + (size_t)row * 128 + q * 4) = v;
    }
}

// ---------------- scatter: Out[dst] += H[src] * dinv[src]*dinv[dst] ----------------
__global__ void k_scatter(const float* __restrict__ H, float* __restrict__ Out,
                          const int* __restrict__ ei, int E) {
    int e = blockIdx.x * (blockDim.x >> 5) + (threadIdx.x >> 5);
    int lane = threadIdx.x & 31;
    if (e >= E) return;
    int s = ei[e];
    int d = ei[E + e];
    float nrm = g_dinv[s] * g_dinv[d];
    float4 v = *(const float4*)(H + (size_t)s * 128 + lane * 4);
    float* o = Out + (size_t)d * 128 + lane * 4;
    atomicAdd(o + 0, v.x * nrm);
    atomicAdd(o + 1, v.y * nrm);
    atomicAdd(o + 2, v.z * nrm);
    atomicAdd(o + 3, v.w * nrm);
}

// ---------------- bias + relu, in place ----------------
__global__ void k_biasrelu(float* __restrict__ X, const float* __restrict__ b, int n) {
    int i = blockIdx.x * blockDim.x + threadIdx.x;  // over n*32 float4s
    int row = i >> 5;
    int q = i & 31;
    if (row < n) {
        float4 v = *(float4*)(X + (size_t)row * 128 + q * 4);
        const float4 bb = *(const float4*)(b + q * 4);
        v.x = fmaxf(v.x + bb.x, 0.f);
        v.y = fmaxf(v.y + bb.y, 0.f);
        v.z = fmaxf(v.z + bb.z, 0.f);
        v.w = fmaxf(v.w + bb.w, 0.f);
        *(float4*)(X + (size_t)row * 128 + q * 4) = v;
    }
}

// ---------------- BN column stats ----------------
__global__ void k_stats(const float* __restrict__ X, int n) {
    int c = threadIdx.x;  // 128 threads, one column each
    float s = 0.f, s2 = 0.f;
    for (int r = blockIdx.x; r < n; r += gridDim.x) {
        float v = X[(size_t)r * 128 + c];
        s += v;
        s2 += v * v;
    }
    atomicAdd(&g_stats[c], s);
    atomicAdd(&g_stats[128 + c], s2);
}

// ---------------- BN apply + relu, in place ----------------
__global__ void k_bnrelu(float* __restrict__ X, const float* __restrict__ gam,
                         const float* __restrict__ bet, int n, float invn) {
    int i = blockIdx.x * blockDim.x + threadIdx.x;
    int row = i >> 5;
    int q = i & 31;
    if (row < n) {
        float4 v = *(float4*)(X + (size_t)row * 128 + q * 4);
        float out[4];
        float* pv = &v.x;
#pragma unroll
        for (int t = 0; t < 4; t++) {
            int c = q * 4 + t;
            float mean = g_stats[c] * invn;
            float var = g_stats[128 + c] * invn - mean * mean;
            float r = (pv[t] - mean) * rsqrtf(var + BN_EPS) * gam[c] + bet[c];
            out[t] = fmaxf(r, 0.f);
        }
        *(float4*)(X + (size_t)row * 128 + q * 4) = make_float4(out[0], out[1], out[2], out[3]);
    }
}

// ---------------- pooling: per-graph sum + count ----------------
__global__ void k_pool(const float* __restrict__ X, const int* __restrict__ batch, int n) {
    int row = blockIdx.x * (blockDim.x >> 5) + (threadIdx.x >> 5);
    int lane = threadIdx.x & 31;
    if (row >= n) return;
    int g = batch[row];
    float4 v = *(const float4*)(X + (size_t)row * 128 + lane * 4);
    float* o = g_pooled + (size_t)g * 128 + lane * 4;
    atomicAdd(o + 0, v.x);
    atomicAdd(o + 1, v.y);
    atomicAdd(o + 2, v.z);
    atomicAdd(o + 3, v.w);
    if (lane == 0) atomicAdd(&g_cnt[g], 1.0f);
}

// ---------------- FC + log_softmax ----------------
__global__ void k_fc(const float* __restrict__ fcw, const float* __restrict__ fcb,
                     float* __restrict__ out) {
    int g = blockIdx.x;
    int c = threadIdx.x;  // 32 threads, first CLS active
    __shared__ float lg[CLS];
    float inv = 1.0f / fmaxf(g_cnt[g], 1.0f);
    if (c < CLS) {
        float a = fcb[c];
        for (int k = 0; k < 128; k++)
            a = fmaf(g_pooled[(size_t)g * 128 + k] * inv, fcw[k * CLS + c], a);
        lg[c] = a;
    }
    __syncthreads();
    if (c < CLS) {
        float mx = -1e30f;
#pragma unroll
        for (int j = 0; j < CLS; j++) mx = fmaxf(mx, lg[j]);
        float se = 0.f;
#pragma unroll
        for (int j = 0; j < CLS; j++) se += expf(lg[j] - mx);
        out[(size_t)g * CLS + c] = lg[c] - mx - logf(se);
    }
}

// ---------------- host launch ----------------
extern "C" void kernel_launch(void* const* d_in, const int* in_sizes, int n_in,
                              void* d_out, int out_size) {
    const float* x = (const float*)d_in[0];
    const int* ei = (const int*)d_in[1];
    const int* batch = (const int*)d_in[2];
    const float* w1 = (const float*)d_in[3];
    const float* b1 = (const float*)d_in[4];
    const float* w2 = (const float*)d_in[5];
    const float* b2 = (const float*)d_in[6];
    const float* w3 = (const float*)d_in[7];
    const float* b3 = (const float*)d_in[8];
    const float* g1 = (const float*)d_in[9];
    const float* be1 = (const float*)d_in[10];
    const float* g2 = (const float*)d_in[11];
    const float* be2 = (const float*)d_in[12];
    const float* fcw = (const float*)d_in[13];
    const float* fcb = (const float*)d_in[14];
    float* out = (float*)d_out;

    int n = in_sizes[0] / D;
    int E = in_sizes[1] / 2;

    float *buf0, *buf1;
    cudaGetSymbolAddress((void**)&buf0, g_buf0);
    cudaGetSymbolAddress((void**)&buf1, g_buf1);

    int initCov = (n > GMAX * D) ? n : GMAX * D;
    k_init<<<(initCov + 255) / 256, 256>>>(n);
    k_deg<<<(E + 255) / 256, 256>>>(ei, E);
    k_dinv<<<(n + 255) / 256, 256>>>(n);

    int gemmBlocks = (n + 127) / 128;
    int elemBlocks = (n * 32 + 255) / 256;   // float4 granularity
    int warpBlocks = (E + 7) / 8;            // 8 warps/block, warp per edge
    int rowWarpBlocks = (n + 7) / 8;
    float invn = 1.0f / (float)n;

    // ---- layer 1: conv1 + relu ----
    k_gemm<<<gemmBlocks, 256>>>(x, w1, buf0, n);
    k_selfinit<<<elemBlocks, 256>>>(buf0, buf1, n);
    k_scatter<<<warpBlocks, 256>>>(buf0, buf1, ei, E);
    k_biasrelu<<<elemBlocks, 256>>>(buf1, b1, n);

    // ---- layer 2: conv2 + relu, bn1 + relu ----
    k_gemm<<<gemmBlocks, 256>>>(buf1, w2, buf0, n);
    k_selfinit<<<elemBlocks, 256>>>(buf0, buf1, n);
    k_scatter<<<warpBlocks, 256>>>(buf0, buf1, ei, E);
    k_biasrelu<<<elemBlocks, 256>>>(buf1, b2, n);
    k_zerostats<<<1, 256>>>();
    k_stats<<<512, 128>>>(buf1, n);
    k_bnrelu<<<elemBlocks, 256>>>(buf1, g1, be1, n, invn);

    // ---- layer 3: conv3 + relu, bn2 + relu ----
    k_gemm<<<gemmBlocks, 256>>>(buf1, w3, buf0, n);
    k_selfinit<<<elemBlocks, 256>>>(buf0, buf1, n);
    k_scatter<<<warpBlocks, 256>>>(buf0, buf1, ei, E);
    k_biasrelu<<<elemBlocks, 256>>>(buf1, b3, n);
    k_zerostats<<<1, 256>>>();
    k_stats<<<512, 128>>>(buf1, n);
    k_bnrelu<<<elemBlocks, 256>>>(buf1, g2, be2, n, invn);

    // ---- pool + fc + log_softmax ----
    k_pool<<<rowWarpBlocks, 256>>>(buf1, batch, n);
    k_fc<<<GMAX, 32>>>(fcw, fcb, out);
}

// round 5
// speedup vs baseline: 2.2682x; 2.2682x over previous
#include <cuda_runtime.h>
#include <math.h>

#define D 128
#define CLS 10
#define GMAX 512
#define NMAX 100096
#define EMAX 1700000
#define BN_EPS 1e-5f

// ---------------- scratch (no allocation allowed) ----------------
__device__ float g_buf0[(size_t)NMAX * D];   // GEMM output H
__device__ float g_buf1[(size_t)NMAX * D];   // aggregation output
__device__ float g_dinv[NMAX];
__device__ float g_statsA[2 * D];            // BN1 column sum, sumsq
__device__ float g_statsB[2 * D];            // BN2 column sum, sumsq
__device__ float g_pooled[GMAX * D];
__device__ float g_cnt[GMAX];

// CSR (dst-indexed)
__device__ int   g_rowptr[NMAX + 1];
__device__ int   g_cursor[NMAX];             // counts, then fill cursors
__device__ int   g_csrc[EMAX];
__device__ float g_cnrm[EMAX];
__device__ int   g_blocksum[160];

// ---------------- init: zero cursors, pooled, cnt, stats ----------------
__global__ void k_init(int n) {
    int i = blockIdx.x * blockDim.x + threadIdx.x;
    if (i < n) g_cursor[i] = 0;
    if (i < GMAX * D) g_pooled[i] = 0.0f;
    if (i < GMAX) g_cnt[i] = 0.0f;
    if (i < 2 * D) { g_statsA[i] = 0.0f; g_statsB[i] = 0.0f; }
}

// ---------------- count in-degree (edges only) ----------------
__global__ void k_count(const int* __restrict__ ei, int E) {
    int e = blockIdx.x * blockDim.x + threadIdx.x;
    if (e < E) atomicAdd(&g_cursor[ei[E + e]], 1);
}

// ---------------- dinv from counts (+1 for self loop) ----------------
__global__ void k_dinv(int n) {
    int i = blockIdx.x * blockDim.x + threadIdx.x;
    if (i < n) g_dinv[i] = rsqrtf((float)(g_cursor[i] + 1));
}

// ---------------- exclusive scan of counts -> rowptr ----------------
// stage A: per-block (1024 elems) local exclusive scan + block total
__global__ void k_scanA(int n) {
    __shared__ int wsum[8];
    int t = threadIdx.x;
    int base = blockIdx.x * 1024 + t * 4;
    int v[4];
#pragma unroll
    for (int j = 0; j < 4; j++) v[j] = (base + j < n) ? g_cursor[base + j] : 0;
    int local = v[0] + v[1] + v[2] + v[3];
    int lane = t & 31, w = t >> 5;
    int x = local;
#pragma unroll
    for (int o = 1; o < 32; o <<= 1) {
        int y = __shfl_up_sync(0xffffffffu, x, o);
        if (lane >= o) x += y;
    }
    if (lane == 31) wsum[w] = x;
    __syncthreads();
    if (t == 0) {
        int acc = 0;
#pragma unroll
        for (int i = 0; i < 8; i++) { int tmp = wsum[i]; wsum[i] = acc; acc += tmp; }
    }
    __syncthreads();
    int run = x - local + wsum[w];   // exclusive prefix of this thread in block
    if (t == 255) g_blocksum[blockIdx.x] = run + local;  // block total
#pragma unroll
    for (int j = 0; j < 4; j++) {
        if (base + j < n) g_rowptr[base + j] = run;
        run += v[j];
    }
}

// stage B: scan block sums (single block)
__global__ void k_scanB(int nb) {
    __shared__ int s[160];
    int t = threadIdx.x;
    if (t < nb) s[t] = g_blocksum[t];
    __syncthreads();
    if (t == 0) {
        int acc = 0;
        for (int i = 0; i < nb; i++) { int tmp = s[i]; s[i] = acc; acc += tmp; }
    }
    __syncthreads();
    if (t < nb) g_blocksum[t] = s[t];
}

// stage C: add block offsets, copy to cursor, close rowptr
__global__ void k_scanC(int n, int E) {
    int i = blockIdx.x * blockDim.x + threadIdx.x;
    if (i < n) {
        int v = g_rowptr[i] + g_blocksum[i >> 10];
        g_rowptr[i] = v;
        g_cursor[i] = v;
    }
    if (i == 0) g_rowptr[n] = E;
}

// ---------------- fill CSR: src index + edge norm ----------------
__global__ void k_fill(const int* __restrict__ ei, int E) {
    int e = blockIdx.x * blockDim.x + threadIdx.x;
    if (e >= E) return;
    int s = ei[e];
    int d = ei[E + e];
    int pos = atomicAdd(&g_cursor[d], 1);
    g_csrc[pos] = s;
    g_cnrm[pos] = g_dinv[s] * g_dinv[d];
}

// ---------------- SGEMM: C[M,128] = A[M,128] @ W[128,128] ----------------
__global__ __launch_bounds__(256, 2) void k_gemm(const float* __restrict__ A,
                                                 const float* __restrict__ W,
                                                 float* __restrict__ Cout, int M) {
    __shared__ float sA[16][132];
    __shared__ float sW[16][128];

    int tid = threadIdx.x;
    int ty = tid >> 4;
    int tx = tid & 15;
    int m0 = blockIdx.x * 128;

    float acc[8][8];
#pragma unroll
    for (int i = 0; i < 8; i++)
#pragma unroll
        for (int j = 0; j < 8; j++) acc[i][j] = 0.0f;

    for (int kk = 0; kk < 128; kk += 16) {
#pragma unroll
        for (int i = 0; i < 2; i++) {
            int idx = tid + i * 256;
            int m = idx >> 2;
            int q = idx & 3;
            float4 v;
            if (m0 + m < M)
                v = *(const float4*)(A + (size_t)(m0 + m) * 128 + kk + q * 4);
            else
                v = make_float4(0.f, 0.f, 0.f, 0.f);
            sA[q * 4 + 0][m] = v.x;
            sA[q * 4 + 1][m] = v.y;
            sA[q * 4 + 2][m] = v.z;
            sA[q * 4 + 3][m] = v.w;
        }
#pragma unroll
        for (int i = 0; i < 2; i++) {
            int idx = tid + i * 256;
            int k = idx >> 5;
            int q = idx & 31;
            *(float4*)&sW[k][q * 4] = *(const float4*)(W + (size_t)(kk + k) * 128 + q * 4);
        }
        __syncthreads();

#pragma unroll
        for (int k = 0; k < 16; k++) {
            float ra[8], rb[8];
            *(float4*)&ra[0] = *(float4*)&sA[k][ty * 8];
            *(float4*)&ra[4] = *(float4*)&sA[k][ty * 8 + 4];
            *(float4*)&rb[0] = *(float4*)&sW[k][tx * 8];
            *(float4*)&rb[4] = *(float4*)&sW[k][tx * 8 + 4];
#pragma unroll
            for (int i = 0; i < 8; i++)
#pragma unroll
                for (int j = 0; j < 8; j++) acc[i][j] = fmaf(ra[i], rb[j], acc[i][j]);
        }
        __syncthreads();
    }

#pragma unroll
    for (int i = 0; i < 8; i++) {
        int m = m0 + ty * 8 + i;
        if (m < M) {
            *(float4*)(Cout + (size_t)m * 128 + tx * 8) =
                make_float4(acc[i][0], acc[i][1], acc[i][2], acc[i][3]);
            *(float4*)(Cout + (size_t)m * 128 + tx * 8 + 4) =
                make_float4(acc[i][4], acc[i][5], acc[i][6], acc[i][7]);
        }
    }
}

// ---------------- gather-aggregate + bias + relu (fused) ----------------
// Out[d] = relu( H[d]*dinv[d]^2 + sum_{e: dst=d} H[src_e]*nrm_e + b )
__global__ __launch_bounds__(256) void k_aggregate(const float* __restrict__ H,
                                                   float* __restrict__ Out,
                                                   const float* __restrict__ bias,
                                                   int n) {
    int row = blockIdx.x * (blockDim.x >> 5) + (threadIdx.x >> 5);
    int lane = threadIdx.x & 31;
    if (row >= n) return;

    float di = g_dinv[row];
    float s2 = di * di;
    float4 acc = *(const float4*)(H + (size_t)row * 128 + lane * 4);
    acc.x *= s2; acc.y *= s2; acc.z *= s2; acc.w *= s2;

    int p = g_rowptr[row];
    int pe = g_rowptr[row + 1];

    for (; p + 1 < pe; p += 2) {
        int s0 = g_csrc[p];
        int s1 = g_csrc[p + 1];
        float n0 = g_cnrm[p];
        float n1 = g_cnrm[p + 1];
        float4 v0 = __ldg((const float4*)(H + (size_t)s0 * 128 + lane * 4));
        float4 v1 = __ldg((const float4*)(H + (size_t)s1 * 128 + lane * 4));
        acc.x = fmaf(v0.x, n0, acc.x); acc.y = fmaf(v0.y, n0, acc.y);
        acc.z = fmaf(v0.z, n0, acc.z); acc.w = fmaf(v0.w, n0, acc.w);
        acc.x = fmaf(v1.x, n1, acc.x); acc.y = fmaf(v1.y, n1, acc.y);
        acc.z = fmaf(v1.z, n1, acc.z); acc.w = fmaf(v1.w, n1, acc.w);
    }
    if (p < pe) {
        int s0 = g_csrc[p];
        float n0 = g_cnrm[p];
        float4 v0 = __ldg((const float4*)(H + (size_t)s0 * 128 + lane * 4));
        acc.x = fmaf(v0.x, n0, acc.x); acc.y = fmaf(v0.y, n0, acc.y);
        acc.z = fmaf(v0.z, n0, acc.z); acc.w = fmaf(v0.w, n0, acc.w);
    }

    const float4 bb = *(const float4*)(bias + lane * 4);
    acc.x = fmaxf(acc.x + bb.x, 0.f);
    acc.y = fmaxf(acc.y + bb.y, 0.f);
    acc.z = fmaxf(acc.z + bb.z, 0.f);
    acc.w = fmaxf(acc.w + bb.w, 0.f);
    *(float4*)(Out + (size_t)row * 128 + lane * 4) = acc;
}

// ---------------- BN column stats ----------------
__global__ void k_stats(const float* __restrict__ X, float* __restrict__ stats, int n) {
    int c = threadIdx.x;  // 128 threads, one column each
    float s = 0.f, s2 = 0.f;
    for (int r = blockIdx.x; r < n; r += gridDim.x) {
        float v = X[(size_t)r * 128 + c];
        s += v;
        s2 += v * v;
    }
    atomicAdd(&stats[c], s);
    atomicAdd(&stats[128 + c], s2);
}

// ---------------- BN apply + relu, in place ----------------
__global__ void k_bnrelu(float* __restrict__ X, const float* __restrict__ stats,
                         const float* __restrict__ gam,
                         const float* __restrict__ bet, int n, float invn) {
    int i = blockIdx.x * blockDim.x + threadIdx.x;
    int row = i >> 5;
    int q = i & 31;
    if (row < n) {
        float4 v = *(float4*)(X + (size_t)row * 128 + q * 4);
        float out[4];
        float* pv = &v.x;
#pragma unroll
        for (int t = 0; t < 4; t++) {
            int c = q * 4 + t;
            float mean = stats[c] * invn;
            float var = stats[128 + c] * invn - mean * mean;
            float r = (pv[t] - mean) * rsqrtf(var + BN_EPS) * gam[c] + bet[c];
            out[t] = fmaxf(r, 0.f);
        }
        *(float4*)(X + (size_t)row * 128 + q * 4) = make_float4(out[0], out[1], out[2], out[3]);
    }
}

// ---------------- pooling: per-graph sum + count ----------------
__global__ void k_pool(const float* __restrict__ X, const int* __restrict__ batch, int n) {
    int row = blockIdx.x * (blockDim.x >> 5) + (threadIdx.x >> 5);
    int lane = threadIdx.x & 31;
    if (row >= n) return;
    int g = batch[row];
    float4 v = *(const float4*)(X + (size_t)row * 128 + lane * 4);
    float* o = g_pooled + (size_t)g * 128 + lane * 4;
    atomicAdd(o + 0, v.x);
    atomicAdd(o + 1, v.y);
    atomicAdd(o + 2, v.z);
    atomicAdd(o + 3, v.w);
    if (lane == 0) atomicAdd(&g_cnt[g], 1.0f);
}

// ---------------- FC + log_softmax ----------------
__global__ void k_fc(const float* __restrict__ fcw, const float* __restrict__ fcb,
                     float* __restrict__ out) {
    int g = blockIdx.x;
    int c = threadIdx.x;
    __shared__ float lg[CLS];
    float inv = 1.0f / fmaxf(g_cnt[g], 1.0f);
    if (c < CLS) {
        float a = fcb[c];
        for (int k = 0; k < 128; k++)
            a = fmaf(g_pooled[(size_t)g * 128 + k] * inv, fcw[k * CLS + c], a);
        lg[c] = a;
    }
    __syncthreads();
    if (c < CLS) {
        float mx = -1e30f;
#pragma unroll
        for (int j = 0; j < CLS; j++) mx = fmaxf(mx, lg[j]);
        float se = 0.f;
#pragma unroll
        for (int j = 0; j < CLS; j++) se += expf(lg[j] - mx);
        out[(size_t)g * CLS + c] = lg[c] - mx - logf(se);
    }
}

// ---------------- host launch ----------------
extern "C" void kernel_launch(void* const* d_in, const int* in_sizes, int n_in,
                              void* d_out, int out_size) {
    const float* x = (const float*)d_in[0];
    const int* ei = (const int*)d_in[1];
    const int* batch = (const int*)d_in[2];
    const float* w1 = (const float*)d_in[3];
    const float* b1 = (const float*)d_in[4];
    const float* w2 = (const float*)d_in[5];
    const float* b2 = (const float*)d_in[6];
    const float* w3 = (const float*)d_in[7];
    const float* b3 = (const float*)d_in[8];
    const float* g1 = (const float*)d_in[9];
    const float* be1 = (const float*)d_in[10];
    const float* g2 = (const float*)d_in[11];
    const float* be2 = (const float*)d_in[12];
    const float* fcw = (const float*)d_in[13];
    const float* fcb = (const float*)d_in[14];
    float* out = (float*)d_out;

    int n = in_sizes[0] / D;
    int E = in_sizes[1] / 2;

    float *buf0, *buf1, *stA, *stB;
    cudaGetSymbolAddress((void**)&buf0, g_buf0);
    cudaGetSymbolAddress((void**)&buf1, g_buf1);
    cudaGetSymbolAddress((void**)&stA, g_statsA);
    cudaGetSymbolAddress((void**)&stB, g_statsB);

    int initCov = (n > GMAX * D) ? n : GMAX * D;
    int nb = (n + 1023) / 1024;

    // ---- CSR build ----
    k_init<<<(initCov + 255) / 256, 256>>>(n);
    k_count<<<(E + 255) / 256, 256>>>(ei, E);
    k_dinv<<<(n + 255) / 256, 256>>>(n);
    k_scanA<<<nb, 256>>>(n);
    k_scanB<<<1, 160>>>(nb);
    k_scanC<<<(n + 255) / 256, 256>>>(n, E);
    k_fill<<<(E + 255) / 256, 256>>>(ei, E);

    int gemmBlocks = (n + 127) / 128;
    int elemBlocks = (n * 32 + 255) / 256;
    int rowWarpBlocks = (n + 7) / 8;
    float invn = 1.0f / (float)n;

    // ---- layer 1: conv1 + relu ----
    k_gemm<<<gemmBlocks, 256>>>(x, w1, buf0, n);
    k_aggregate<<<rowWarpBlocks, 256>>>(buf0, buf1, b1, n);

    // ---- layer 2: conv2 + relu, bn1 + relu ----
    k_gemm<<<gemmBlocks, 256>>>(buf1, w2, buf0, n);
    k_aggregate<<<rowWarpBlocks, 256>>>(buf0, buf1, b2, n);
    k_stats<<<512, 128>>>(buf1, stA, n);
    k_bnrelu<<<elemBlocks, 256>>>(buf1, stA, g1, be1, n, invn);

    // ---- layer 3: conv3 + relu, bn2 + relu ----
    k_gemm<<<gemmBlocks, 256>>>(buf1, w3, buf0, n);
    k_aggregate<<<rowWarpBlocks, 256>>>(buf0, buf1, b3, n);
    k_stats<<<512, 128>>>(buf1, stB, n);
    k_bnrelu<<<elemBlocks, 256>>>(buf1, stB, g2, be2, n, invn);

    // ---- pool + fc + log_softmax ----
    k_pool<<<rowWarpBlocks, 256>>>(buf1, batch, n);
    k_fc<<<GMAX, 32>>>(fcw, fcb, out);
}

// round 6
// speedup vs baseline: 3.5992x; 1.5869x over previous
#include <cuda_runtime.h>
#include <cuda_fp16.h>
#include <math.h>

#define D 128
#define CLS 10
#define GMAX 512
#define NMAX 100096
#define EMAX 1700000
#define BN_EPS 1e-5f
#define AGG_BLOCKS 1184
#define POOL_BLOCKS 296

// ---------------- scratch (no allocation allowed) ----------------
__device__ __half g_bufh[(size_t)NMAX * D];   // GEMM output H (fp16, gathered)
__device__ float  g_buf1[(size_t)NMAX * D];   // aggregation output (fp32)
__device__ float  g_dinv[NMAX];
__device__ float  g_statsA[2 * D];
__device__ float  g_statsB[2 * D];
__device__ float  g_bnsc1[D], g_bnsh1[D];
__device__ float  g_bnsc2[D], g_bnsh2[D];
__device__ float  g_pooled[GMAX * D];
__device__ float  g_cnt[GMAX];

struct __align__(8) Edge { int s; float w; };
__device__ int   g_rowptr[NMAX + 1];
__device__ int   g_cursor[NMAX];
__device__ Edge  g_edge[EMAX];
__device__ int   g_blocksum[160];

// ---------------- init ----------------
__global__ void k_init(int n) {
    int i = blockIdx.x * blockDim.x + threadIdx.x;
    if (i < n) g_cursor[i] = 0;
    if (i < GMAX * D) g_pooled[i] = 0.0f;
    if (i < GMAX) g_cnt[i] = 0.0f;
    if (i < 2 * D) { g_statsA[i] = 0.0f; g_statsB[i] = 0.0f; }
}

__global__ void k_count(const int* __restrict__ ei, int E) {
    int e = blockIdx.x * blockDim.x + threadIdx.x;
    if (e < E) atomicAdd(&g_cursor[ei[E + e]], 1);
}

__global__ void k_dinv(int n) {
    int i = blockIdx.x * blockDim.x + threadIdx.x;
    if (i < n) g_dinv[i] = rsqrtf((float)(g_cursor[i] + 1));
}

// ---------------- exclusive scan of counts -> rowptr ----------------
__global__ void k_scanA(int n) {
    __shared__ int wsum[8];
    int t = threadIdx.x;
    int base = blockIdx.x * 1024 + t * 4;
    int v[4];
#pragma unroll
    for (int j = 0; j < 4; j++) v[j] = (base + j < n) ? g_cursor[base + j] : 0;
    int local = v[0] + v[1] + v[2] + v[3];
    int lane = t & 31, w = t >> 5;
    int x = local;
#pragma unroll
    for (int o = 1; o < 32; o <<= 1) {
        int y = __shfl_up_sync(0xffffffffu, x, o);
        if (lane >= o) x += y;
    }
    if (lane == 31) wsum[w] = x;
    __syncthreads();
    if (t == 0) {
        int acc = 0;
#pragma unroll
        for (int i = 0; i < 8; i++) { int tmp = wsum[i]; wsum[i] = acc; acc += tmp; }
    }
    __syncthreads();
    int run = x - local + wsum[w];
    if (t == 255) g_blocksum[blockIdx.x] = run + local;
#pragma unroll
    for (int j = 0; j < 4; j++) {
        if (base + j < n) g_rowptr[base + j] = run;
        run += v[j];
    }
}

__global__ void k_scanB(int nb) {
    __shared__ int s[160];
    int t = threadIdx.x;
    if (t < nb) s[t] = g_blocksum[t];
    __syncthreads();
    if (t == 0) {
        int acc = 0;
        for (int i = 0; i < nb; i++) { int tmp = s[i]; s[i] = acc; acc += tmp; }
    }
    __syncthreads();
    if (t < nb) g_blocksum[t] = s[t];
}

__global__ void k_scanC(int n, int E) {
    int i = blockIdx.x * blockDim.x + threadIdx.x;
    if (i < n) {
        int v = g_rowptr[i] + g_blocksum[i >> 10];
        g_rowptr[i] = v;
        g_cursor[i] = v;
    }
    if (i == 0) g_rowptr[n] = E;
}

__global__ void k_fill(const int* __restrict__ ei, int E) {
    int e = blockIdx.x * blockDim.x + threadIdx.x;
    if (e >= E) return;
    int s = ei[e];
    int d = ei[E + e];
    int pos = atomicAdd(&g_cursor[d], 1);
    Edge ed;
    ed.s = s;
    ed.w = g_dinv[s] * g_dinv[d];
    g_edge[pos] = ed;
}

// ---------------- SGEMM: Hh[M,128](fp16) = bnrelu?(A[M,128]) @ W[128,128] ----------------
template<bool BNA>
__global__ __launch_bounds__(256, 2) void k_gemm(const float* __restrict__ A,
                                                 const float* __restrict__ W,
                                                 __half* __restrict__ Hh, int M) {
    __shared__ float sA[16][132];
    __shared__ float sW[16][128];

    int tid = threadIdx.x;
    int ty = tid >> 4;
    int tx = tid & 15;
    int m0 = blockIdx.x * 128;

    float acc[8][8];
#pragma unroll
    for (int i = 0; i < 8; i++)
#pragma unroll
        for (int j = 0; j < 8; j++) acc[i][j] = 0.0f;

    for (int kk = 0; kk < 128; kk += 16) {
#pragma unroll
        for (int i = 0; i < 2; i++) {
            int idx = tid + i * 256;
            int m = idx >> 2;
            int q = idx & 3;
            float4 v;
            if (m0 + m < M)
                v = *(const float4*)(A + (size_t)(m0 + m) * 128 + kk + q * 4);
            else
                v = make_float4(0.f, 0.f, 0.f, 0.f);
            if (BNA) {
                float4 sc = *(const float4*)(g_bnsc1 + kk + q * 4);
                float4 sf = *(const float4*)(g_bnsh1 + kk + q * 4);
                v.x = fmaxf(fmaf(v.x, sc.x, sf.x), 0.f);
                v.y = fmaxf(fmaf(v.y, sc.y, sf.y), 0.f);
                v.z = fmaxf(fmaf(v.z, sc.z, sf.z), 0.f);
                v.w = fmaxf(fmaf(v.w, sc.w, sf.w), 0.f);
            }
            sA[q * 4 + 0][m] = v.x;
            sA[q * 4 + 1][m] = v.y;
            sA[q * 4 + 2][m] = v.z;
            sA[q * 4 + 3][m] = v.w;
        }
#pragma unroll
        for (int i = 0; i < 2; i++) {
            int idx = tid + i * 256;
            int k = idx >> 5;
            int q = idx & 31;
            *(float4*)&sW[k][q * 4] = *(const float4*)(W + (size_t)(kk + k) * 128 + q * 4);
        }
        __syncthreads();

#pragma unroll
        for (int k = 0; k < 16; k++) {
            float ra[8], rb[8];
            *(float4*)&ra[0] = *(float4*)&sA[k][ty * 8];
            *(float4*)&ra[4] = *(float4*)&sA[k][ty * 8 + 4];
            *(float4*)&rb[0] = *(float4*)&sW[k][tx * 8];
            *(float4*)&rb[4] = *(float4*)&sW[k][tx * 8 + 4];
#pragma unroll
            for (int i = 0; i < 8; i++)
#pragma unroll
                for (int j = 0; j < 8; j++) acc[i][j] = fmaf(ra[i], rb[j], acc[i][j]);
        }
        __syncthreads();
    }

#pragma unroll
    for (int i = 0; i < 8; i++) {
        int m = m0 + ty * 8 + i;
        if (m < M) {
            __half2 h0 = __floats2half2_rn(acc[i][0], acc[i][1]);
            __half2 h1 = __floats2half2_rn(acc[i][2], acc[i][3]);
            __half2 h2 = __floats2half2_rn(acc[i][4], acc[i][5]);
            __half2 h3 = __floats2half2_rn(acc[i][6], acc[i][7]);
            uint4 u = make_uint4(*(unsigned*)&h0, *(unsigned*)&h1,
                                 *(unsigned*)&h2, *(unsigned*)&h3);
            *(uint4*)(Hh + (size_t)m * 128 + tx * 8) = u;
        }
    }
}

// ---------------- gather-aggregate + bias + relu (+ optional BN stats) ----------------
// Out[d] = relu( Hh[d]*dinv[d]^2 + sum_{e: dst=d} Hh[src_e]*nrm_e + b )
template<bool STATS>
__global__ __launch_bounds__(256) void k_aggregate(const __half* __restrict__ Hh,
                                                   float* __restrict__ Out,
                                                   const float* __restrict__ bias,
                                                   float* __restrict__ stats,
                                                   int n) {
    int lane = threadIdx.x & 31;
    int gw = blockIdx.x * 8 + (threadIdx.x >> 5);
    int totalW = gridDim.x * 8;

    const float4 bb = *(const float4*)(bias + lane * 4);
    float s[4] = {0.f, 0.f, 0.f, 0.f};
    float s2[4] = {0.f, 0.f, 0.f, 0.f};

    for (int row = gw; row < n; row += totalW) {
        float di = g_dinv[row];
        float sf = di * di;
        uint2 rs = *(const uint2*)(Hh + (size_t)row * 128 + lane * 4);
        float2 a0 = __half22float2(*(__half2*)&rs.x);
        float2 a1 = __half22float2(*(__half2*)&rs.y);
        float4 acc = make_float4(a0.x * sf, a0.y * sf, a1.x * sf, a1.y * sf);

        int p = g_rowptr[row];
        int pe = g_rowptr[row + 1];

        for (; p + 2 <= pe; p += 2) {
            Edge e0 = g_edge[p];
            Edge e1 = g_edge[p + 1];
            uint2 r0 = *(const uint2*)(Hh + (size_t)e0.s * 128 + lane * 4);
            uint2 r1 = *(const uint2*)(Hh + (size_t)e1.s * 128 + lane * 4);
            float2 v0a = __half22float2(*(__half2*)&r0.x);
            float2 v0b = __half22float2(*(__half2*)&r0.y);
            float2 v1a = __half22float2(*(__half2*)&r1.x);
            float2 v1b = __half22float2(*(__half2*)&r1.y);
            acc.x = fmaf(v0a.x, e0.w, acc.x); acc.y = fmaf(v0a.y, e0.w, acc.y);
            acc.z = fmaf(v0b.x, e0.w, acc.z); acc.w = fmaf(v0b.y, e0.w, acc.w);
            acc.x = fmaf(v1a.x, e1.w, acc.x); acc.y = fmaf(v1a.y, e1.w, acc.y);
            acc.z = fmaf(v1b.x, e1.w, acc.z); acc.w = fmaf(v1b.y, e1.w, acc.w);
        }
        if (p < pe) {
            Edge e0 = g_edge[p];
            uint2 r0 = *(const uint2*)(Hh + (size_t)e0.s * 128 + lane * 4);
            float2 v0a = __half22float2(*(__half2*)&r0.x);
            float2 v0b = __half22float2(*(__half2*)&r0.y);
            acc.x = fmaf(v0a.x, e0.w, acc.x); acc.y = fmaf(v0a.y, e0.w, acc.y);
            acc.z = fmaf(v0b.x, e0.w, acc.z); acc.w = fmaf(v0b.y, e0.w, acc.w);
        }

        acc.x = fmaxf(acc.x + bb.x, 0.f);
        acc.y = fmaxf(acc.y + bb.y, 0.f);
        acc.z = fmaxf(acc.z + bb.z, 0.f);
        acc.w = fmaxf(acc.w + bb.w, 0.f);
        *(float4*)(Out + (size_t)row * 128 + lane * 4) = acc;

        if (STATS) {
            s[0] += acc.x; s2[0] += acc.x * acc.x;
            s[1] += acc.y; s2[1] += acc.y * acc.y;
            s[2] += acc.z; s2[2] += acc.z * acc.z;
            s[3] += acc.w; s2[3] += acc.w * acc.w;
        }
    }

    if (STATS) {
        __shared__ float sh[256];
        sh[threadIdx.x] = 0.f;
        __syncthreads();
#pragma unroll
        for (int j = 0; j < 4; j++) {
            atomicAdd(&sh[lane * 4 + j], s[j]);
            atomicAdd(&sh[128 + lane * 4 + j], s2[j]);
        }
        __syncthreads();
        atomicAdd(&stats[threadIdx.x], sh[threadIdx.x]);
    }
}

// ---------------- BN prep: scale/shift from stats ----------------
__global__ void k_bnprep(const float* __restrict__ stats, const float* __restrict__ gam,
                         const float* __restrict__ bet, float* __restrict__ scale,
                         float* __restrict__ shift, float invn) {
    int c = threadIdx.x;
    float mean = stats[c] * invn;
    float var = stats[128 + c] * invn - mean * mean;
    float sc = rsqrtf(var + BN_EPS) * gam[c];
    scale[c] = sc;
    shift[c] = bet[c] - mean * sc;
}

// ---------------- pool (segmented; batch sorted) + fused BN2+relu ----------------
__global__ __launch_bounds__(256) void k_pool(const float* __restrict__ X,
                                              const int* __restrict__ batch, int n) {
    int lane = threadIdx.x & 31;
    int w = blockIdx.x * 8 + (threadIdx.x >> 5);
    int totalW = gridDim.x * 8;
    int chunk = (n + totalW - 1) / totalW;
    int r0 = w * chunk;
    int r1 = min(r0 + chunk, n);
    if (r0 >= n) return;

    float4 sc = *(const float4*)(g_bnsc2 + lane * 4);
    float4 sh = *(const float4*)(g_bnsh2 + lane * 4);

    int curg = batch[r0];
    float4 acc = make_float4(0.f, 0.f, 0.f, 0.f);
    float c = 0.f;
    for (int r = r0; r < r1; r++) {
        int g = batch[r];
        if (g != curg) {
            float* o = g_pooled + (size_t)curg * 128 + lane * 4;
            atomicAdd(o + 0, acc.x); atomicAdd(o + 1, acc.y);
            atomicAdd(o + 2, acc.z); atomicAdd(o + 3, acc.w);
            if (lane == 0) atomicAdd(&g_cnt[curg], c);
            acc = make_float4(0.f, 0.f, 0.f, 0.f);
            c = 0.f;
            curg = g;
        }
        float4 v = *(const float4*)(X + (size_t)r * 128 + lane * 4);
        acc.x += fmaxf(fmaf(v.x, sc.x, sh.x), 0.f);
        acc.y += fmaxf(fmaf(v.y, sc.y, sh.y), 0.f);
        acc.z += fmaxf(fmaf(v.z, sc.z, sh.z), 0.f);
        acc.w += fmaxf(fmaf(v.w, sc.w, sh.w), 0.f);
        c += 1.f;
    }
    float* o = g_pooled + (size_t)curg * 128 + lane * 4;
    atomicAdd(o + 0, acc.x); atomicAdd(o + 1, acc.y);
    atomicAdd(o + 2, acc.z); atomicAdd(o + 3, acc.w);
    if (lane == 0) atomicAdd(&g_cnt[curg], c);
}

// ---------------- FC + log_softmax ----------------
__global__ void k_fc(const float* __restrict__ fcw, const float* __restrict__ fcb,
                     float* __restrict__ out) {
    int g = blockIdx.x;
    int c = threadIdx.x;
    __shared__ float lg[CLS];
    float inv = 1.0f / fmaxf(g_cnt[g], 1.0f);
    if (c < CLS) {
        float a = fcb[c];
        for (int k = 0; k < 128; k++)
            a = fmaf(g_pooled[(size_t)g * 128 + k] * inv, fcw[k * CLS + c], a);
        lg[c] = a;
    }
    __syncthreads();
    if (c < CLS) {
        float mx = -1e30f;
#pragma unroll
        for (int j = 0; j < CLS; j++) mx = fmaxf(mx, lg[j]);
        float se = 0.f;
#pragma unroll
        for (int j = 0; j < CLS; j++) se += expf(lg[j] - mx);
        out[(size_t)g * CLS + c] = lg[c] - mx - logf(se);
    }
}

// ---------------- host launch ----------------
extern "C" void kernel_launch(void* const* d_in, const int* in_sizes, int n_in,
                              void* d_out, int out_size) {
    const float* x = (const float*)d_in[0];
    const int* ei = (const int*)d_in[1];
    const int* batch = (const int*)d_in[2];
    const float* w1 = (const float*)d_in[3];
    const float* b1 = (const float*)d_in[4];
    const float* w2 = (const float*)d_in[5];
    const float* b2 = (const float*)d_in[6];
    const float* w3 = (const float*)d_in[7];
    const float* b3 = (const float*)d_in[8];
    const float* g1 = (const float*)d_in[9];
    const float* be1 = (const float*)d_in[10];
    const float* g2 = (const float*)d_in[11];
    const float* be2 = (const float*)d_in[12];
    const float* fcw = (const float*)d_in[13];
    const float* fcb = (const float*)d_in[14];
    float* out = (float*)d_out;

    int n = in_sizes[0] / D;
    int E = in_sizes[1] / 2;

    __half* bufh;
    float *buf1, *stA, *stB, *sc1, *sh1, *sc2, *sh2;
    cudaGetSymbolAddress((void**)&bufh, g_bufh);
    cudaGetSymbolAddress((void**)&buf1, g_buf1);
    cudaGetSymbolAddress((void**)&stA, g_statsA);
    cudaGetSymbolAddress((void**)&stB, g_statsB);
    cudaGetSymbolAddress((void**)&sc1, g_bnsc1);
    cudaGetSymbolAddress((void**)&sh1, g_bnsh1);
    cudaGetSymbolAddress((void**)&sc2, g_bnsc2);
    cudaGetSymbolAddress((void**)&sh2, g_bnsh2);

    int initCov = (n > GMAX * D) ? n : GMAX * D;
    int nb = (n + 1023) / 1024;

    // ---- CSR build ----
    k_init<<<(initCov + 255) / 256, 256>>>(n);
    k_count<<<(E + 255) / 256, 256>>>(ei, E);
    k_dinv<<<(n + 255) / 256, 256>>>(n);
    k_scanA<<<nb, 256>>>(n);
    k_scanB<<<1, 160>>>(nb);
    k_scanC<<<(n + 255) / 256, 256>>>(n, E);
    k_fill<<<(E + 255) / 256, 256>>>(ei, E);

    int gemmBlocks = (n + 127) / 128;
    float invn = 1.0f / (float)n;

    // ---- layer 1: conv1 + relu ----
    k_gemm<false><<<gemmBlocks, 256>>>(x, w1, bufh, n);
    k_aggregate<false><<<AGG_BLOCKS, 256>>>(bufh, buf1, b1, nullptr, n);

    // ---- layer 2: conv2 + relu (stats for bn1 fused) ----
    k_gemm<false><<<gemmBlocks, 256>>>(buf1, w2, bufh, n);
    k_aggregate<true><<<AGG_BLOCKS, 256>>>(bufh, buf1, b2, stA, n);
    k_bnprep<<<1, 128>>>(stA, g1, be1, sc1, sh1, invn);

    // ---- layer 3: conv3 (bn1+relu fused into A load) + relu (stats for bn2 fused) ----
    k_gemm<true><<<gemmBlocks, 256>>>(buf1, w3, bufh, n);
    k_aggregate<true><<<AGG_BLOCKS, 256>>>(bufh, buf1, b3, stB, n);
    k_bnprep<<<1, 128>>>(stB, g2, be2, sc2, sh2, invn);

    // ---- pool (bn2+relu fused) + fc + log_softmax ----
    k_pool<<<POOL_BLOCKS, 256>>>(buf1, batch, n);
    k_fc<<<GMAX, 32>>>(fcw, fcb, out);
}

// round 8
// speedup vs baseline: 6.0149x; 1.6712x over previous
#include <cuda_runtime.h>
#include <cuda_fp16.h>
#include <math.h>

#define D 128
#define CLS 10
#define GMAX 512
#define NMAX 100096
#define EMAX 1700000
#define BN_EPS 1e-5f
#define AGG_BLOCKS 1184
#define POOL_BLOCKS 296
#define GEMM_SMEM (2 * 128 * 136 * 2)   // two fp16 tiles, stride 136

// ---------------- scratch (no allocation allowed) ----------------
__device__ __half g_bufx[(size_t)NMAX * D];   // fp16 copy of input x
__device__ __half g_bufh[(size_t)NMAX * D];   // GEMM output H (fp16, gathered)
__device__ __half g_buf1h[(size_t)NMAX * D];  // aggregation output (fp16)
__device__ __half g_wt[3 * D * D];            // fp16 transposed weights [n][k]
__device__ float  g_dinv[NMAX];
__device__ float  g_statsA[2 * D];
__device__ float  g_statsB[2 * D];
__device__ float  g_bnsc1[D], g_bnsh1[D];
__device__ float  g_bnsc2[D], g_bnsh2[D];
__device__ float  g_pooled[GMAX * D];
__device__ float  g_cnt[GMAX];

struct __align__(8) Edge { int s; float w; };
__device__ int   g_rowptr[NMAX + 1];
__device__ int   g_cursor[NMAX];
__device__ Edge  g_edge[EMAX];
__device__ int   g_blocksum[160];

// ---------------- init ----------------
__global__ void k_init(int n) {
    int i = blockIdx.x * blockDim.x + threadIdx.x;
    if (i < n) g_cursor[i] = 0;
    if (i < GMAX * D) g_pooled[i] = 0.0f;
    if (i < GMAX) g_cnt[i] = 0.0f;
    if (i < 2 * D) { g_statsA[i] = 0.0f; g_statsB[i] = 0.0f; }
}

__global__ void k_count(const int* __restrict__ ei, int E) {
    int e = blockIdx.x * blockDim.x + threadIdx.x;
    if (e < E) atomicAdd(&g_cursor[ei[E + e]], 1);
}

__global__ void k_dinv(int n) {
    int i = blockIdx.x * blockDim.x + threadIdx.x;
    if (i < n) g_dinv[i] = rsqrtf((float)(g_cursor[i] + 1));
}

// ---------------- exclusive scan of counts -> rowptr ----------------
__global__ void k_scanA(int n) {
    __shared__ int wsum[8];
    int t = threadIdx.x;
    int base = blockIdx.x * 1024 + t * 4;
    int v[4];
#pragma unroll
    for (int j = 0; j < 4; j++) v[j] = (base + j < n) ? g_cursor[base + j] : 0;
    int local = v[0] + v[1] + v[2] + v[3];
    int lane = t & 31, w = t >> 5;
    int x = local;
#pragma unroll
    for (int o = 1; o < 32; o <<= 1) {
        int y = __shfl_up_sync(0xffffffffu, x, o);
        if (lane >= o) x += y;
    }
    if (lane == 31) wsum[w] = x;
    __syncthreads();
    if (t == 0) {
        int acc = 0;
#pragma unroll
        for (int i = 0; i < 8; i++) { int tmp = wsum[i]; wsum[i] = acc; acc += tmp; }
    }
    __syncthreads();
    int run = x - local + wsum[w];
    if (t == 255) g_blocksum[blockIdx.x] = run + local;
#pragma unroll
    for (int j = 0; j < 4; j++) {
        if (base + j < n) g_rowptr[base + j] = run;
        run += v[j];
    }
}

__global__ void k_scanB(int nb) {
    __shared__ int s[160];
    int t = threadIdx.x;
    if (t < nb) s[t] = g_blocksum[t];
    __syncthreads();
    if (t == 0) {
        int acc = 0;
        for (int i = 0; i < nb; i++) { int tmp = s[i]; s[i] = acc; acc += tmp; }
    }
    __syncthreads();
    if (t < nb) g_blocksum[t] = s[t];
}

__global__ void k_scanC(int n, int E) {
    int i = blockIdx.x * blockDim.x + threadIdx.x;
    if (i < n) {
        int v = g_rowptr[i] + g_blocksum[i >> 10];
        g_rowptr[i] = v;
        g_cursor[i] = v;
    }
    if (i == 0) g_rowptr[n] = E;
}

__global__ void k_fill(const int* __restrict__ ei, int E) {
    int e = blockIdx.x * blockDim.x + threadIdx.x;
    if (e >= E) return;
    int s = ei[e];
    int d = ei[E + e];
    int pos = atomicAdd(&g_cursor[d], 1);
    Edge ed;
    ed.s = s;
    ed.w = g_dinv[s] * g_dinv[d];
    g_edge[pos] = ed;
}

// ---------------- conversions ----------------
__global__ void k_xconv(const float* __restrict__ x, __half* __restrict__ xh, int n) {
    int i = blockIdx.x * blockDim.x + threadIdx.x;  // over n*32 float4s
    if (i < n * 32) {
        float4 v = *(const float4*)(x + (size_t)i * 4);
        __half2 h0 = __floats2half2_rn(v.x, v.y);
        __half2 h1 = __floats2half2_rn(v.z, v.w);
        *(uint2*)(xh + (size_t)i * 4) = make_uint2(*(unsigned*)&h0, *(unsigned*)&h1);
    }
}

// transpose + fp16: g_wt[which][n*128+k] = w[k*128+n]
__global__ void k_wconv(const float* __restrict__ w1, const float* __restrict__ w2,
                        const float* __restrict__ w3) {
    int i = blockIdx.x * blockDim.x + threadIdx.x;
    if (i >= 3 * D * D) return;
    int which = i >> 14;
    const float* w = (which == 0) ? w1 : (which == 1) ? w2 : w3;
    int idx = i & (D * D - 1);
    int k = idx >> 7, nn = idx & 127;
    g_wt[which * D * D + nn * D + k] = __float2half(w[k * D + nn]);
}

// ---------------- tensor-core GEMM: Hh[M,128] = bnrelu?(A[M,128]) @ W ----------------
// A fp16 row-major; Wt fp16 [n][k]; mma m16n8k16 fp32 accum.
template<bool BNA>
__global__ __launch_bounds__(256) void k_gemm_tc(const __half* __restrict__ A,
                                                 const __half* __restrict__ Wt,
                                                 __half* __restrict__ Hh, int M) {
    extern __shared__ __half sm[];
    __half* sA = sm;                 // [128][136]
    __half* sB = sm + 128 * 136;     // [128][136]  (Wt rows = n)

    int tid = threadIdx.x;
    int m0 = blockIdx.x * 128;

    // load A tile (2048 uint4, 8 per thread), optional BN1 affine+relu
#pragma unroll
    for (int i = 0; i < 8; i++) {
        int idx = tid + i * 256;
        int r = idx >> 4;
        int c8 = (idx & 15) << 3;
        uint4 u = make_uint4(0u, 0u, 0u, 0u);
        if (m0 + r < M) u = *(const uint4*)(A + (size_t)(m0 + r) * 128 + c8);
        if (BNA) {
            __half2* hp = (__half2*)&u;
#pragma unroll
            for (int j = 0; j < 4; j++) {
                float2 v = __half22float2(hp[j]);
                int c = c8 + j * 2;
                v.x = fmaxf(fmaf(v.x, g_bnsc1[c], g_bnsh1[c]), 0.f);
                v.y = fmaxf(fmaf(v.y, g_bnsc1[c + 1], g_bnsh1[c + 1]), 0.f);
                hp[j] = __floats2half2_rn(v.x, v.y);
            }
        }
        *(uint4*)(sA + r * 136 + c8) = u;
    }
    // load W tile
#pragma unroll
    for (int i = 0; i < 8; i++) {
        int idx = tid + i * 256;
        int r = idx >> 4;
        int c8 = (idx & 15) << 3;
        *(uint4*)(sB + r * 136 + c8) = *(const uint4*)(Wt + r * 128 + c8);
    }
    __syncthreads();

    int w = tid >> 5, lane = tid & 31;
    int g = lane >> 2, tg = lane & 3;
    int wm = (w >> 2) * 64;      // 0 / 64
    int wn = (w & 3) * 32;       // 0 / 32 / 64 / 96

    float acc[4][4][4];
#pragma unroll
    for (int mi = 0; mi < 4; mi++)
#pragma unroll
        for (int ni = 0; ni < 4; ni++)
#pragma unroll
            for (int j = 0; j < 4; j++) acc[mi][ni][j] = 0.f;

#pragma unroll
    for (int k0 = 0; k0 < 128; k0 += 16) {
        unsigned af[4][4], bf[4][2];
#pragma unroll
        for (int mi = 0; mi < 4; mi++) {
            const __half* base = sA + (wm + mi * 16 + g) * 136 + k0 + tg * 2;
            af[mi][0] = *(const unsigned*)(base);
            af[mi][1] = *(const unsigned*)(base + 8 * 136);
            af[mi][2] = *(const unsigned*)(base + 8);
            af[mi][3] = *(const unsigned*)(base + 8 * 136 + 8);
        }
#pragma unroll
        for (int ni = 0; ni < 4; ni++) {
            const __half* base = sB + (wn + ni * 8 + g) * 136 + k0 + tg * 2;
            bf[ni][0] = *(const unsigned*)(base);
            bf[ni][1] = *(const unsigned*)(base + 8);
        }
#pragma unroll
        for (int mi = 0; mi < 4; mi++)
#pragma unroll
            for (int ni = 0; ni < 4; ni++) {
                asm volatile(
                    "mma.sync.aligned.m16n8k16.row.col.f32.f16.f16.f32 "
                    "{%0,%1,%2,%3}, {%4,%5,%6,%7}, {%8,%9}, {%0,%1,%2,%3};"
                    : "+f"(acc[mi][ni][0]), "+f"(acc[mi][ni][1]),
                      "+f"(acc[mi][ni][2]), "+f"(acc[mi][ni][3])
                    : "r"(af[mi][0]), "r"(af[mi][1]), "r"(af[mi][2]), "r"(af[mi][3]),
                      "r"(bf[ni][0]), "r"(bf[ni][1]));
            }
    }

    // epilogue: fp16 stores
#pragma unroll
    for (int mi = 0; mi < 4; mi++) {
        int r0 = m0 + wm + mi * 16 + g;
        int r1 = r0 + 8;
#pragma unroll
        for (int ni = 0; ni < 4; ni++) {
            int c = wn + ni * 8 + tg * 2;
            if (r0 < M) {
                __half2 h = __floats2half2_rn(acc[mi][ni][0], acc[mi][ni][1]);
                *(__half2*)(Hh + (size_t)r0 * 128 + c) = h;
            }
            if (r1 < M) {
                __half2 h = __floats2half2_rn(acc[mi][ni][2], acc[mi][ni][3]);
                *(__half2*)(Hh + (size_t)r1 * 128 + c) = h;
            }
        }
    }
}

// ---------------- gather-aggregate + bias + relu (+ optional BN stats) ----------------
template<bool STATS>
__global__ __launch_bounds__(256) void k_aggregate(const __half* __restrict__ Hh,
                                                   __half* __restrict__ Outh,
                                                   const float* __restrict__ bias,
                                                   float* __restrict__ stats,
                                                   int n) {
    int lane = threadIdx.x & 31;
    int gw = blockIdx.x * 8 + (threadIdx.x >> 5);
    int totalW = gridDim.x * 8;

    const float4 bb = *(const float4*)(bias + lane * 4);
    float s[4] = {0.f, 0.f, 0.f, 0.f};
    float s2[4] = {0.f, 0.f, 0.f, 0.f};

    for (int row = gw; row < n; row += totalW) {
        float di = g_dinv[row];
        float sf = di * di;
        uint2 rs = *(const uint2*)(Hh + (size_t)row * 128 + lane * 4);
        float2 a0 = __half22float2(*(__half2*)&rs.x);
        float2 a1 = __half22float2(*(__half2*)&rs.y);
        float4 acc = make_float4(a0.x * sf, a0.y * sf, a1.x * sf, a1.y * sf);

        int p = g_rowptr[row];
        int pe = g_rowptr[row + 1];

        for (; p + 2 <= pe; p += 2) {
            Edge e0 = g_edge[p];
            Edge e1 = g_edge[p + 1];
            uint2 r0 = *(const uint2*)(Hh + (size_t)e0.s * 128 + lane * 4);
            uint2 r1 = *(const uint2*)(Hh + (size_t)e1.s * 128 + lane * 4);
            float2 v0a = __half22float2(*(__half2*)&r0.x);
            float2 v0b = __half22float2(*(__half2*)&r0.y);
            float2 v1a = __half22float2(*(__half2*)&r1.x);
            float2 v1b = __half22float2(*(__half2*)&r1.y);
            acc.x = fmaf(v0a.x, e0.w, acc.x); acc.y = fmaf(v0a.y, e0.w, acc.y);
            acc.z = fmaf(v0b.x, e0.w, acc.z); acc.w = fmaf(v0b.y, e0.w, acc.w);
            acc.x = fmaf(v1a.x, e1.w, acc.x); acc.y = fmaf(v1a.y, e1.w, acc.y);
            acc.z = fmaf(v1b.x, e1.w, acc.z); acc.w = fmaf(v1b.y, e1.w, acc.w);
        }
        if (p < pe) {
            Edge e0 = g_edge[p];
            uint2 r0 = *(const uint2*)(Hh + (size_t)e0.s * 128 + lane * 4);
            float2 v0a = __half22float2(*(__half2*)&r0.x);
            float2 v0b = __half22float2(*(__half2*)&r0.y);
            acc.x = fmaf(v0a.x, e0.w, acc.x); acc.y = fmaf(v0a.y, e0.w, acc.y);
            acc.z = fmaf(v0b.x, e0.w, acc.z); acc.w = fmaf(v0b.y, e0.w, acc.w);
        }

        acc.x = fmaxf(acc.x + bb.x, 0.f);
        acc.y = fmaxf(acc.y + bb.y, 0.f);
        acc.z = fmaxf(acc.z + bb.z, 0.f);
        acc.w = fmaxf(acc.w + bb.w, 0.f);

        __half2 o0 = __floats2half2_rn(acc.x, acc.y);
        __half2 o1 = __floats2half2_rn(acc.z, acc.w);
        *(uint2*)(Outh + (size_t)row * 128 + lane * 4) =
            make_uint2(*(unsigned*)&o0, *(unsigned*)&o1);

        if (STATS) {
            s[0] += acc.x; s2[0] += acc.x * acc.x;
            s[1] += acc.y; s2[1] += acc.y * acc.y;
            s[2] += acc.z; s2[2] += acc.z * acc.z;
            s[3] += acc.w; s2[3] += acc.w * acc.w;
        }
    }

    if (STATS) {
        __shared__ float sh[256];
        sh[threadIdx.x] = 0.f;
        __syncthreads();
#pragma unroll
        for (int j = 0; j < 4; j++) {
            atomicAdd(&sh[lane * 4 + j], s[j]);
            atomicAdd(&sh[128 + lane * 4 + j], s2[j]);
        }
        __syncthreads();
        atomicAdd(&stats[threadIdx.x], sh[threadIdx.x]);
    }
}

// ---------------- BN prep ----------------
__global__ void k_bnprep(const float* __restrict__ stats, const float* __restrict__ gam,
                         const float* __restrict__ bet, float* __restrict__ scale,
                         float* __restrict__ shift, float invn) {
    int c = threadIdx.x;
    float mean = stats[c] * invn;
    float var = stats[128 + c] * invn - mean * mean;
    float sc = rsqrtf(var + BN_EPS) * gam[c];
    scale[c] = sc;
    shift[c] = bet[c] - mean * sc;
}

// ---------------- pool (segmented) + fused BN2+relu ----------------
__global__ __launch_bounds__(256) void k_pool(const __half* __restrict__ Xh,
                                              const int* __restrict__ batch, int n) {
    int lane = threadIdx.x & 31;
    int w = blockIdx.x * 8 + (threadIdx.x >> 5);
    int totalW = gridDim.x * 8;
    int chunk = (n + totalW - 1) / totalW;
    int r0 = w * chunk;
    int r1 = min(r0 + chunk, n);
    if (r0 >= n) return;

    float4 sc = *(const float4*)(g_bnsc2 + lane * 4);
    float4 sh = *(const float4*)(g_bnsh2 + lane * 4);

    int curg = batch[r0];
    float4 acc = make_float4(0.f, 0.f, 0.f, 0.f);
    float c = 0.f;
    for (int r = r0; r < r1; r++) {
        int g = batch[r];
        if (g != curg) {
            float* o = g_pooled + (size_t)curg * 128 + lane * 4;
            atomicAdd(o + 0, acc.x); atomicAdd(o + 1, acc.y);
            atomicAdd(o + 2, acc.z); atomicAdd(o + 3, acc.w);
            if (lane == 0) atomicAdd(&g_cnt[curg], c);
            acc = make_float4(0.f, 0.f, 0.f, 0.f);
            c = 0.f;
            curg = g;
        }
        uint2 rv = *(const uint2*)(Xh + (size_t)r * 128 + lane * 4);
        float2 va = __half22float2(*(__half2*)&rv.x);
        float2 vb = __half22float2(*(__half2*)&rv.y);
        acc.x += fmaxf(fmaf(va.x, sc.x, sh.x), 0.f);
        acc.y += fmaxf(fmaf(va.y, sc.y, sh.y), 0.f);
        acc.z += fmaxf(fmaf(vb.x, sc.z, sh.z), 0.f);
        acc.w += fmaxf(fmaf(vb.y, sc.w, sh.w), 0.f);
        c += 1.f;
    }
    float* o = g_pooled + (size_t)curg * 128 + lane * 4;
    atomicAdd(o + 0, acc.x); atomicAdd(o + 1, acc.y);
    atomicAdd(o + 2, acc.z); atomicAdd(o + 3, acc.w);
    if (lane == 0) atomicAdd(&g_cnt[curg], c);
}

// ---------------- FC + log_softmax ----------------
__global__ void k_fc(const float* __restrict__ fcw, const float* __restrict__ fcb,
                     float* __restrict__ out) {
    int g = blockIdx.x;
    int c = threadIdx.x;
    __shared__ float lg[CLS];
    float inv = 1.0f / fmaxf(g_cnt[g], 1.0f);
    if (c < CLS) {
        float a = fcb[c];
        for (int k = 0; k < 128; k++)
            a = fmaf(g_pooled[(size_t)g * 128 + k] * inv, fcw[k * CLS + c], a);
        lg[c] = a;
    }
    __syncthreads();
    if (c < CLS) {
        float mx = -1e30f;
#pragma unroll
        for (int j = 0; j < CLS; j++) mx = fmaxf(mx, lg[j]);
        float se = 0.f;
#pragma unroll
        for (int j = 0; j < CLS; j++) se += expf(lg[j] - mx);
        out[(size_t)g * CLS + c] = lg[c] - mx - logf(se);
    }
}

// ---------------- host launch ----------------
extern "C" void kernel_launch(void* const* d_in, const int* in_sizes, int n_in,
                              void* d_out, int out_size) {
    const float* x = (const float*)d_in[0];
    const int* ei = (const int*)d_in[1];
    const int* batch = (const int*)d_in[2];
    const float* w1 = (const float*)d_in[3];
    const float* b1 = (const float*)d_in[4];
    const float* w2 = (const float*)d_in[5];
    const float* b2 = (const float*)d_in[6];
    const float* w3 = (const float*)d_in[7];
    const float* b3 = (const float*)d_in[8];
    const float* g1 = (const float*)d_in[9];
    const float* be1 = (const float*)d_in[10];
    const float* g2 = (const float*)d_in[11];
    const float* be2 = (const float*)d_in[12];
    const float* fcw = (const float*)d_in[13];
    const float* fcb = (const float*)d_in[14];
    float* out = (float*)d_out;

    int n = in_sizes[0] / D;
    int E = in_sizes[1] / 2;

    __half *bufx, *bufh, *buf1h, *wt;
    float *stA, *stB, *sc1, *sh1, *sc2, *sh2;
    cudaGetSymbolAddress((void**)&bufx, g_bufx);
    cudaGetSymbolAddress((void**)&bufh, g_bufh);
    cudaGetSymbolAddress((void**)&buf1h, g_buf1h);
    cudaGetSymbolAddress((void**)&wt, g_wt);
    cudaGetSymbolAddress((void**)&stA, g_statsA);
    cudaGetSymbolAddress((void**)&stB, g_statsB);
    cudaGetSymbolAddress((void**)&sc1, g_bnsc1);
    cudaGetSymbolAddress((void**)&sh1, g_bnsh1);
    cudaGetSymbolAddress((void**)&sc2, g_bnsc2);
    cudaGetSymbolAddress((void**)&sh2, g_bnsh2);

    cudaFuncSetAttribute(k_gemm_tc<false>, cudaFuncAttributeMaxDynamicSharedMemorySize, GEMM_SMEM);
    cudaFuncSetAttribute(k_gemm_tc<true>, cudaFuncAttributeMaxDynamicSharedMemorySize, GEMM_SMEM);

    int initCov = (n > GMAX * D) ? n : GMAX * D;
    int nb = (n + 1023) / 1024;

    // ---- CSR build + conversions ----
    k_init<<<(initCov + 255) / 256, 256>>>(n);
    k_count<<<(E + 255) / 256, 256>>>(ei, E);
    k_dinv<<<(n + 255) / 256, 256>>>(n);
    k_scanA<<<nb, 256>>>(n);
    k_scanB<<<1, 160>>>(nb);
    k_scanC<<<(n + 255) / 256, 256>>>(n, E);
    k_fill<<<(E + 255) / 256, 256>>>(ei, E);
    k_xconv<<<(n * 32 + 255) / 256, 256>>>(x, bufx, n);
    k_wconv<<<(3 * D * D + 255) / 256, 256>>>(w1, w2, w3);

    int gemmBlocks = (n + 127) / 128;
    float invn = 1.0f / (float)n;

    // ---- layer 1 ----
    k_gemm_tc<false><<<gemmBlocks, 256, GEMM_SMEM>>>(bufx, wt, bufh, n);
    k_aggregate<false><<<AGG_BLOCKS, 256>>>(bufh, buf1h, b1, nullptr, n);

    // ---- layer 2 (stats for bn1 fused) ----
    k_gemm_tc<false><<<gemmBlocks, 256, GEMM_SMEM>>>(buf1h, wt + D * D, bufh, n);
    k_aggregate<true><<<AGG_BLOCKS, 256>>>(bufh, buf1h, b2, stA, n);
    k_bnprep<<<1, 128>>>(stA, g1, be1, sc1, sh1, invn);

    // ---- layer 3 (bn1+relu fused into A load; stats for bn2 fused) ----
    k_gemm_tc<true><<<gemmBlocks, 256, GEMM_SMEM>>>(buf1h, wt + 2 * D * D, bufh, n);
    k_aggregate<true><<<AGG_BLOCKS, 256>>>(bufh, buf1h, b3, stB, n);
    k_bnprep<<<1, 128>>>(stB, g2, be2, sc2, sh2, invn);

    // ---- pool (bn2+relu fused) + fc + log_softmax ----
    k_pool<<<POOL_BLOCKS, 256>>>(buf1h, batch, n);
    k_fc<<<GMAX, 32>>>(fcw, fcb, out);
}